// round 6
// baseline (speedup 1.0000x reference)
#include <cuda_runtime.h>

#define FULL 0xFFFFFFFFu

__device__ __forceinline__ unsigned long long pack2(float a, float b) {
    unsigned long long r;
    asm("mov.b64 %0, {%1, %2};" : "=l"(r) : "f"(a), "f"(b));
    return r;
}
__device__ __forceinline__ void unpack2(unsigned long long p, float& a, float& b) {
    asm("mov.b64 {%0, %1}, %2;" : "=f"(a), "=f"(b) : "l"(p));
}
__device__ __forceinline__ unsigned long long fma2(unsigned long long a,
                                                   unsigned long long b,
                                                   unsigned long long c) {
    unsigned long long d;
    asm("fma.rn.f32x2 %0, %1, %2, %3;" : "=l"(d) : "l"(a), "l"(b), "l"(c));
    return d;
}
__device__ __forceinline__ unsigned long long add2(unsigned long long a,
                                                   unsigned long long b) {
    unsigned long long d;
    asm("add.rn.f32x2 %0, %1, %2;" : "=l"(d) : "l"(a), "l"(b));
    return d;
}

__device__ __forceinline__ float fast_sigmoid(float x) {
    return __fdividef(1.0f, 1.0f + __expf(-x));
}

// One CTA per TWO batches, 288 threads, grid 128 (one CTA/SM, single wave).
// Threads 0..255: layer-0. Warps 0-3 handle batch 0, warps 4-7 batch 1 --
// two warps per SMSP, so one warp's fma burst hides the other's nonlinear
// tail (MUFU/SHFL/LDS latency). Thread within batch = (unit u, type);
// type0 owns gate columns (i,j), type1 owns (f,o); weights register-resident
// as f32x2 pairs, identical across the two batch warp-groups.
// Threads 256..287 (warp 8): layer-1 (units=1) + dense for both batches
// (lane halves), one step lagged. One __syncthreads per step.
__global__ __launch_bounds__(288, 1)
void lstm_stack_kernel(const float* __restrict__ x,
                       const float* __restrict__ W0,
                       const float* __restrict__ b0,
                       const float* __restrict__ W1,
                       const float* __restrict__ b1,
                       const float* __restrict__ Wd,
                       const float* __restrict__ bd,
                       float* __restrict__ out)
{
    constexpr int T = 2048;

    const int bb   = blockIdx.x;      // batch pair
    const int tid  = threadIdx.x;
    const int lane = tid & 31;
    const int wid  = tid >> 5;

    __shared__ __align__(16) float x_sh[2][T];
    __shared__ __align__(16) float h_sh[2][2][64];   // [buffer][batch][unit]
    __shared__ float red[9];
    __shared__ float inv_sh[2];

    // ---- Phase 0: load both x tiles, l2-normalize over time ----
    for (int bi = 0; bi < 2; ++bi) {
        const float* xb = x + (2 * bb + bi) * T;
        float ps = 0.f;
        for (int i = tid; i < T; i += 288) {
            float v = xb[i];
            x_sh[bi][i] = v;
            ps = fmaf(v, v, ps);
        }
        #pragma unroll
        for (int o = 16; o > 0; o >>= 1) ps += __shfl_xor_sync(FULL, ps, o);
        if (lane == 0) red[wid] = ps;
        __syncthreads();
        if (tid == 0) {
            float s = 0.f;
            #pragma unroll
            for (int i = 0; i < 9; ++i) s += red[i];
            inv_sh[bi] = rsqrtf(fmaxf(s, 1e-12f));
        }
        __syncthreads();               // also protects red[] reuse
    }
    {
        float i0 = inv_sh[0], i1 = inv_sh[1];
        for (int i = tid; i < T; i += 288) {
            x_sh[0][i] *= i0;
            x_sh[1][i] *= i1;
        }
    }
    if (tid < 128) ((float*)h_sh[0])[tid] = 0.f;   // h_{-1} = 0, both batches
    // (ordered by the sync at the top of the main loop)

    // ---- Per-thread persistent state / weights ----
    const int bsel = (tid >> 7) & 1;    // 0: warps 0-3, 1: warps 4-7
    const int tid2 = tid & 127;
    const int u    = tid2 >> 1;
    const int type = tid2 & 1;          // 0: (i,j)   1: (f,o)
    unsigned long long wpa[32], wpb[32];
    float wxa = 0.f, wxb = 0.f, ba = 0.f, bb2 = 0.f;
    float c0 = 0.f;

    // layer-1 (warp 8) state: lanes 0-15 -> batch0, 16-31 -> batch1
    const int l1b  = lane >> 4;
    const int l1g  = lane & 3;
    const int l1bk = (lane >> 2) & 3;
    float w1r[16];
    float w1h = 0.f, b1v = 0.f, wdv = 0.f, bdv = 0.f;
    float c1 = 0.f, h1 = 0.f;

    if (tid < 256) {
        const int ca = u + (type ? 128 : 0);   // i or f column
        const int cb = ca + 64;                // j or o column
        wxa = W0[ca];
        wxb = W0[cb];
        ba  = b0[ca] + (type ? 1.0f : 0.0f);   // fold FORGET_BIAS
        bb2 = b0[cb];
        #pragma unroll
        for (int p = 0; p < 32; ++p) {
            wpa[p] = pack2(W0[(1 + 2 * p) * 256 + ca], W0[(2 + 2 * p) * 256 + ca]);
            wpb[p] = pack2(W0[(1 + 2 * p) * 256 + cb], W0[(2 + 2 * p) * 256 + cb]);
        }
    } else {
        #pragma unroll
        for (int j = 0; j < 16; ++j)
            w1r[j] = W1[(l1bk + 4 * j) * 4 + l1g];
        w1h = W1[64 * 4 + l1g];
        b1v = b1[l1g];
        wdv = Wd[0];
        bdv = bd[0];
    }

    // ---- Main recurrence: t = 0..T. Layer-0 active for t<T, layer-1
    // processes step t-1 (final iteration drains layer-1). ----
    #pragma unroll 1
    for (int t = 0; t <= T; ++t) {
        __syncthreads();                 // h_sh[t&1] = h_{t-1} now valid
        const int cur = t & 1;
        if (tid < 256) {
            if (t < T) {
                float xt = x_sh[bsel][t];
                const ulonglong2* hp = (const ulonglong2*)h_sh[cur][bsel];
                unsigned long long zero = pack2(0.f, 0.f);
                unsigned long long a0 = pack2(fmaf(xt, wxa, ba), 0.f);
                unsigned long long a1 = zero;
                unsigned long long e0 = pack2(fmaf(xt, wxb, bb2), 0.f);
                unsigned long long e1 = zero;
                #pragma unroll
                for (int i = 0; i < 16; ++i) {
                    ulonglong2 hv = hp[i];   // one LDS.128 feeds both gates
                    a0 = fma2(hv.x, wpa[2 * i],     a0);
                    a1 = fma2(hv.y, wpa[2 * i + 1], a1);
                    e0 = fma2(hv.x, wpb[2 * i],     e0);
                    e1 = fma2(hv.y, wpb[2 * i + 1], e1);
                }
                float za, zb;
                {
                    float lo, hi;
                    unpack2(add2(a0, a1), lo, hi); za = lo + hi;
                    unpack2(add2(e0, e1), lo, hi); zb = lo + hi;
                }

                // type0: sa = sigma(i), rb = tanh(j); sends sa*rb.
                // type1: sa = sigma(f+1) (bias folded), rb = sigma(o); sends sa.
                float sa = fast_sigmoid(za);
                float sb = fast_sigmoid(type ? zb : (zb + zb));
                float rb = type ? sb : (2.f * sb - 1.f);
                float send = type ? sa : (sa * rb);
                float recv = __shfl_xor_sync(FULL, send, 1);
                float fg  = type ? sa : recv;
                float inc = type ? recv : send;
                c0 = fmaf(fg, c0, inc);
                float th = 2.f * fast_sigmoid(c0 + c0) - 1.f;
                float h  = rb * th;       // valid on type1 (rb = sigma(o))
                if (type) h_sh[cur ^ 1][bsel][u] = h;
            }
        } else {
            if (t >= 1) {
                // layer-1 for step s = t-1, input h_sh[cur][l1b]
                const float* hv = h_sh[cur][l1b];
                float p = 0.f;
                #pragma unroll
                for (int j = 0; j < 16; ++j)
                    p = fmaf(hv[l1bk + 4 * j], w1r[j], p);
                p += __shfl_xor_sync(FULL, p, 4);    // stays within 16-lane half
                p += __shfl_xor_sync(FULL, p, 8);
                float z1 = fmaf(h1, w1h, p + b1v);

                float zz = (l1g == 2) ? (z1 + 1.0f) : z1;
                float sv = (l1g == 1) ? (zz + zz) : zz;
                float sg = fast_sigmoid(sv);
                float r  = (l1g == 1) ? (2.f * sg - 1.f) : sg;

                float ri = __shfl_sync(FULL, r, 0, 4);
                float rj = __shfl_sync(FULL, r, 1, 4);
                float rf = __shfl_sync(FULL, r, 2, 4);
                float ro = __shfl_sync(FULL, r, 3, 4);
                c1 = fmaf(rf, c1, ri * rj);
                float th = 2.f * fast_sigmoid(c1 + c1) - 1.f;
                h1 = ro * th;
                if ((lane & 15) == 0)
                    out[(2 * bb + l1b) * T + (t - 1)] = fmaf(h1, wdv, bdv);
            }
        }
    }
}

extern "C" void kernel_launch(void* const* d_in, const int* in_sizes, int n_in,
                              void* d_out, int out_size) {
    const float* x  = (const float*)d_in[0];
    const float* W0 = (const float*)d_in[1];
    const float* b0 = (const float*)d_in[2];
    const float* W1 = (const float*)d_in[3];
    const float* b1 = (const float*)d_in[4];
    const float* Wd = (const float*)d_in[5];
    const float* bd = (const float*)d_in[6];
    float* out = (float*)d_out;
    lstm_stack_kernel<<<128, 288>>>(x, W0, b0, W1, b1, Wd, bd, out);
}